// round 1
// baseline (speedup 1.0000x reference)
#include <cuda_runtime.h>

#define NMAX 100000
#define EMAX 1600000
#define F 128

// ---------------- scratch (device globals; no allocation allowed) ----------------
__device__ double g_doutw[NMAX];           // weighted out-degree (sum of w over src)
__device__ double g_dinw[NMAX];            // weighted in-degree  (sum of w over dst)
__device__ int    g_cntin[NMAX];           // unweighted in-degree
__device__ int    g_cntout[NMAX];          // unweighted out-degree
__device__ float  g_wraw[EMAX];            // raw edge weight
__device__ int    g_rowstart[NMAX + 1];    // CSR (by dst) row starts
__device__ int    g_cursor[NMAX];          // fill cursors
__device__ float  g_normin[NMAX];          // deg_in^-0.5  (clamped >= 1)
__device__ float  g_normout[NMAX];         // deg_out^-0.5 (clamped >= 1)
__device__ float  g_rdoutw[NMAX];          // rsqrt(weighted out-degree)
__device__ float  g_rdinw[NMAX];           // rsqrt(weighted in-degree)
__device__ int2   g_csr[EMAX];             // {src, float_bits(w_normalized)} sorted by dst
__device__ float  g_h [(size_t)NMAX * F];  // (x * norm_out) @ W1
__device__ float  g_h1[(size_t)NMAX * F];  // relu(agg1*norm_in + b1) * norm_out
__device__ float  g_h2[(size_t)NMAX * F];  // g_h1 @ W2

// ---------------- K0: zero accumulators ----------------
__global__ void k_zero(int N) {
    int i = blockIdx.x * blockDim.x + threadIdx.x;
    if (i < N) {
        g_doutw[i] = 0.0; g_dinw[i] = 0.0;
        g_cntin[i] = 0;   g_cntout[i] = 0;
    }
}

// ---------------- K1: edge weights + degree sums ----------------
__global__ void k_edge_w(const float* __restrict__ ef, const float* __restrict__ Wef,
                         const float* __restrict__ bef,
                         const int* __restrict__ src, const int* __restrict__ dst, int E) {
    int e = blockIdx.x * blockDim.x + threadIdx.x;
    if (e >= E) return;
    const float4* p = (const float4*)(ef + (size_t)e * 16);
    float acc = __ldg(bef);
#pragma unroll
    for (int q = 0; q < 4; q++) {
        float4 v = __ldg(p + q);
        acc += v.x * __ldg(Wef + q * 4 + 0) + v.y * __ldg(Wef + q * 4 + 1)
             + v.z * __ldg(Wef + q * 4 + 2) + v.w * __ldg(Wef + q * 4 + 3);
    }
    g_wraw[e] = acc;
    int s = src[e], d = dst[e];
    atomicAdd(&g_doutw[s], (double)acc);
    atomicAdd(&g_dinw[d],  (double)acc);
    atomicAdd(&g_cntout[s], 1);
    atomicAdd(&g_cntin[d],  1);
}

// ---------------- K2: single-block exclusive scan of in-degrees -> rowstart ----------------
__global__ void k_scan(int N, int E) {
    __shared__ int warpsums[32];
    __shared__ int s_carry;
    int tid = threadIdx.x;
    int lane = tid & 31, wid = tid >> 5;
    if (tid == 0) s_carry = 0;
    __syncthreads();
    for (int base = 0; base < N; base += 1024) {
        int i = base + tid;
        int v = (i < N) ? g_cntin[i] : 0;
        int x = v;
#pragma unroll
        for (int o = 1; o < 32; o <<= 1) {
            int y = __shfl_up_sync(0xffffffffu, x, o);
            if (lane >= o) x += y;
        }
        if (lane == 31) warpsums[wid] = x;
        __syncthreads();
        if (wid == 0) {
            int w = warpsums[lane];
#pragma unroll
            for (int o = 1; o < 32; o <<= 1) {
                int y = __shfl_up_sync(0xffffffffu, w, o);
                if (lane >= o) w += y;
            }
            warpsums[lane] = w;
        }
        __syncthreads();
        int excl = (x - v) + (wid > 0 ? warpsums[wid - 1] : 0) + s_carry;
        if (i < N) g_rowstart[i] = excl;
        __syncthreads();
        if (tid == 0) s_carry += warpsums[31];
        __syncthreads();
    }
    if (tid == 0) g_rowstart[N] = E;
}

// ---------------- K3: node-side normalizers + cursors ----------------
__global__ void k_node(int N) {
    int i = blockIdx.x * blockDim.x + threadIdx.x;
    if (i >= N) return;
    int cin = g_cntin[i], cout = g_cntout[i];
    g_normin[i]  = rsqrtf((float)(cin  > 1 ? cin  : 1));
    g_normout[i] = rsqrtf((float)(cout > 1 ? cout : 1));
    float dw = (float)g_doutw[i];
    float iw = (float)g_dinw[i];
    g_rdoutw[i] = dw > 0.f ? rsqrtf(dw) : 0.f;
    g_rdinw[i]  = iw > 0.f ? rsqrtf(iw) : 0.f;
    g_cursor[i] = g_rowstart[i];
}

// ---------------- K4: fill CSR (by dst) with normalized edge weights ----------------
__global__ void k_fill(const int* __restrict__ src, const int* __restrict__ dst, int E) {
    int e = blockIdx.x * blockDim.x + threadIdx.x;
    if (e >= E) return;
    int s = src[e], d = dst[e];
    int pos = atomicAdd(&g_cursor[d], 1);
    float w = g_wraw[e] * g_rdoutw[s] * g_rdinw[d];
    g_csr[pos] = make_int2(s, __float_as_int(w));
}

// ---------------- K5: GEMM  C[N,128] = A[N,128] @ W[128,128]  (optionally * norm_out[row]) ----
// BM=64, BN=128, BK=16, 256 threads, 8x4 microtile per thread.
template <bool SCALE_ROWS>
__global__ __launch_bounds__(256)
void k_gemm(const float* __restrict__ A, const float* __restrict__ W,
            float* __restrict__ C, int N) {
    __shared__ float As[16][65];   // padded: conflict-free transposed stores
    __shared__ float Bs[16][128];

    int tid = threadIdx.x;
    int block_row = blockIdx.x * 64;
    int tx = tid & 31;       // col group: cols tx*4 .. tx*4+3
    int ty = tid >> 5;       // row group: rows ty*8 .. ty*8+7

    int am = tid >> 2;             // 0..63 (A row within tile)
    int ak = (tid & 3) * 4;        // 0,4,8,12 (A k offset)
    int bk = tid >> 5;             // 0..7
    int bj = (tid & 31) * 4;       // 0..124

    float acc[8][4];
#pragma unroll
    for (int r = 0; r < 8; r++)
#pragma unroll
        for (int c = 0; c < 4; c++) acc[r][c] = 0.f;

    for (int k0 = 0; k0 < 128; k0 += 16) {
        int arow = block_row + am;
        float4 av = make_float4(0.f, 0.f, 0.f, 0.f);
        if (arow < N) av = *(const float4*)(A + (size_t)arow * F + k0 + ak);
        As[ak + 0][am] = av.x; As[ak + 1][am] = av.y;
        As[ak + 2][am] = av.z; As[ak + 3][am] = av.w;

        *(float4*)&Bs[bk][bj]     = *(const float4*)(W + (size_t)(k0 + bk) * F + bj);
        *(float4*)&Bs[bk + 8][bj] = *(const float4*)(W + (size_t)(k0 + bk + 8) * F + bj);
        __syncthreads();

#pragma unroll
        for (int kk = 0; kk < 16; kk++) {
            float4 b = *(const float4*)&Bs[kk][tx * 4];
#pragma unroll
            for (int r = 0; r < 8; r++) {
                float a = As[kk][ty * 8 + r];
                acc[r][0] += a * b.x; acc[r][1] += a * b.y;
                acc[r][2] += a * b.z; acc[r][3] += a * b.w;
            }
        }
        __syncthreads();
    }

#pragma unroll
    for (int r = 0; r < 8; r++) {
        int row = block_row + ty * 8 + r;
        if (row < N) {
            float s = SCALE_ROWS ? g_normout[row] : 1.f;
            float4 o;
            o.x = acc[r][0] * s; o.y = acc[r][1] * s;
            o.z = acc[r][2] * s; o.w = acc[r][3] * s;
            *(float4*)(C + (size_t)row * F + tx * 4) = o;
        }
    }
}

// ---------------- K6: warp-per-node CSR aggregation ----------------
// MODE 1: out = relu(acc*norm_in + b) * norm_out     (layer 1; norm_out pre-folded for GEMM2)
// MODE 0: out = acc*norm_in + b                      (layer 2; final output)
template <int MODE>
__global__ __launch_bounds__(256)
void k_agg(const float* __restrict__ H, const float* __restrict__ bias,
           float* __restrict__ OUT, int N) {
    int gw = (blockIdx.x * blockDim.x + threadIdx.x) >> 5;
    if (gw >= N) return;
    int lane = threadIdx.x & 31;
    int i0 = g_rowstart[gw], i1 = g_rowstart[gw + 1];

    // double accumulation: order-insensitive to the float ulp (CSR fill order is
    // atomic-nondeterministic, so this keeps the output deterministic).
    double a0 = 0.0, a1 = 0.0, a2 = 0.0, a3 = 0.0;
    for (int i = i0; i < i1; i++) {
        int2 ew = g_csr[i];                        // broadcast (uniform address per warp)
        float wv = __int_as_float(ew.y);
        float4 h = *(const float4*)(H + (size_t)ew.x * F + lane * 4);  // coalesced 512B row
        a0 += (double)(wv * h.x);
        a1 += (double)(wv * h.y);
        a2 += (double)(wv * h.z);
        a3 += (double)(wv * h.w);
    }
    float ni = g_normin[gw];
    float4 b = *(const float4*)(bias + lane * 4);
    float o0 = (float)a0 * ni + b.x;
    float o1 = (float)a1 * ni + b.y;
    float o2 = (float)a2 * ni + b.z;
    float o3 = (float)a3 * ni + b.w;
    if (MODE == 1) {
        float so = g_normout[gw];
        o0 = fmaxf(o0, 0.f) * so; o1 = fmaxf(o1, 0.f) * so;
        o2 = fmaxf(o2, 0.f) * so; o3 = fmaxf(o3, 0.f) * so;
    }
    float4 o; o.x = o0; o.y = o1; o.z = o2; o.w = o3;
    *(float4*)(OUT + (size_t)gw * F + lane * 4) = o;
}

// ---------------- host ----------------
extern "C" void kernel_launch(void* const* d_in, const int* in_sizes, int n_in,
                              void* d_out, int out_size) {
    const float* node_feats = (const float*)d_in[0];
    const float* edge_feats = (const float*)d_in[1];
    const float* W_ef       = (const float*)d_in[2];
    const float* b_ef       = (const float*)d_in[3];
    const float* W1         = (const float*)d_in[4];
    const float* b1         = (const float*)d_in[5];
    const float* W2         = (const float*)d_in[6];
    const float* b2         = (const float*)d_in[7];
    const int*   src        = (const int*)d_in[8];
    const int*   dst        = (const int*)d_in[9];
    int N = in_sizes[0] / F;
    int E = in_sizes[8];
    float* out = (float*)d_out;

    float *ph, *ph1, *ph2;
    cudaGetSymbolAddress((void**)&ph,  g_h);
    cudaGetSymbolAddress((void**)&ph1, g_h1);
    cudaGetSymbolAddress((void**)&ph2, g_h2);

    int nbN = (N + 255) / 256;
    int nbE = (E + 255) / 256;
    int nbG = (N + 63) / 64;
    int nbA = (N * 32 + 255) / 256;

    k_zero  <<<nbN, 256>>>(N);
    k_edge_w<<<nbE, 256>>>(edge_feats, W_ef, b_ef, src, dst, E);
    k_scan  <<<1, 1024>>>(N, E);
    k_node  <<<nbN, 256>>>(N);
    k_fill  <<<nbE, 256>>>(src, dst, E);

    k_gemm<true> <<<nbG, 256>>>(node_feats, W1, ph,  N);  // h = (x @ W1) * norm_out
    k_agg<1>     <<<nbA, 256>>>(ph,  b1, ph1, N);          // h1 = relu(agg*ni + b1) * norm_out
    k_gemm<false><<<nbG, 256>>>(ph1, W2, ph2, N);          // h2 = h1 @ W2
    k_agg<0>     <<<nbA, 256>>>(ph2, b2, out, N);          // out = agg*ni + b2
}